// round 3
// baseline (speedup 1.0000x reference)
#include <cuda_runtime.h>
#include <cuda_bf16.h>
#include <cstdint>

#define HF 128
#define WF 192
#define NA 9
#define HW (HF*WF)               // 24576
#define NTOT (HW*NA)             // 221184
#define TOPN 6000
#define POSTN 300
#define NB 94                    // ceil(6000/64)
#define CAND_MAX 16384
#define RB 128                   // rank block threads
#define KPT 2                    // keys per thread in k_rank
#define JCHUNKS 16
#define JCHUNK (CAND_MAX/JCHUNKS)

__constant__ float c_anchors[NA][4] = {
    {-84.f,  -40.f,  99.f,  55.f},
    {-176.f, -88.f,  191.f, 103.f},
    {-360.f, -184.f, 375.f, 199.f},
    {-56.f,  -56.f,  71.f,  71.f},
    {-120.f, -120.f, 135.f, 135.f},
    {-248.f, -248.f, 263.f, 263.f},
    {-36.f,  -80.f,  51.f,  95.f},
    {-80.f,  -168.f, 95.f,  183.f},
    {-168.f, -344.f, 183.f, 359.f}
};

__device__ unsigned long long g_keys[NTOT];
__device__ float4 g_boxes[NTOT];          // indexed by thread-order t = a*HW + k
__device__ unsigned int g_hist[65536];
__device__ unsigned int g_thresh;
__device__ unsigned int g_cand_count;
__device__ unsigned long long g_cand[CAND_MAX];
__device__ unsigned int g_rank[CAND_MAX];
__device__ float4 g_top_boxes[TOPN];
__device__ int g_vld[TOPN];

// ---------------- K1: decode + keys + histogram (coalesced) ----------------
__global__ void k_score_box(const float* __restrict__ scores,
                            const float* __restrict__ deltas,
                            const float* __restrict__ im_info) {
    int t = blockIdx.x * blockDim.x + threadIdx.x;
    if (t >= NTOT) return;
    int a = t / HW;
    int k = t - a * HW;          // spatial index; base == k (y-major flatten)
    // anchor/shift side uses meshgrid 'ij' quirk: shift row k -> (x=k/128, y=k%128)
    int xs = k >> 7;
    int ys = k & 127;
    int i_ref = k * NA + a;      // reference flatten order (tiebreak + identity)

    float sc = scores[(NA + a) * HW + k];
    float dx = deltas[(4*a + 0) * HW + k];
    float dy = deltas[(4*a + 1) * HW + k];
    float dw = deltas[(4*a + 2) * HW + k];
    float dh = deltas[(4*a + 3) * HW + k];

    float sx = 16.f * (float)xs;
    float sy = 16.f * (float)ys;
    float ax1 = c_anchors[a][0] + sx;
    float ay1 = c_anchors[a][1] + sy;
    float ax2 = c_anchors[a][2] + sx;
    float ay2 = c_anchors[a][3] + sy;

    float w = ax2 - ax1 + 1.f;
    float h = ay2 - ay1 + 1.f;
    float cx = ax1 + 0.5f * w;
    float cy = ay1 + 0.5f * h;

    float pcx = dx * w + cx;
    float pcy = dy * h + cy;
    float pw = expf(dw) * w;
    float ph = expf(dh) * h;

    float x1 = pcx - 0.5f * pw;
    float y1 = pcy - 0.5f * ph;
    float x2 = pcx + 0.5f * pw;
    float y2 = pcy + 0.5f * ph;

    float im0 = im_info[0], im1 = im_info[1], im2 = im_info[2];
    x1 = fminf(fmaxf(x1, 0.f), im1 - 1.f);
    x2 = fminf(fmaxf(x2, 0.f), im1 - 1.f);
    y1 = fminf(fmaxf(y1, 0.f), im0 - 1.f);
    y2 = fminf(fmaxf(y2, 0.f), im0 - 1.f);

    float ms = 16.f * im2;
    bool valid = (x2 - x1 + 1.f >= ms) && (y2 - y1 + 1.f >= ms);

    unsigned int srt;
    if (valid) {
        unsigned int b = __float_as_uint(sc);
        srt = (b & 0x80000000u) ? ~b : (b | 0x80000000u);
    } else {
        srt = 0x007FFFFFu;   // flip(-inf)
    }
    unsigned long long key =
        ((unsigned long long)srt << 32) | (0xFFFFFFFFu - (unsigned int)i_ref);
    g_keys[t] = key;
    g_boxes[t] = make_float4(x1, y1, x2, y2);
    atomicAdd(&g_hist[srt >> 16], 1u);
}

// ---------------- K2: find top-6000 threshold bucket ----------------
__global__ void k_thresh() {
    __shared__ unsigned int s[256];
    __shared__ int gsel;
    __shared__ unsigned int above_s;
    int t = threadIdx.x;
    unsigned int sum = 0;
#pragma unroll 8
    for (int b = 0; b < 256; b++) sum += g_hist[t * 256 + b];
    s[t] = sum;
    __syncthreads();
    for (int off = 1; off < 256; off <<= 1) {
        unsigned int v = (t + off < 256) ? s[t + off] : 0u;
        __syncthreads();
        s[t] += v;
        __syncthreads();
    }
    unsigned int nxt = (t == 255) ? 0u : s[t + 1];
    if (s[t] >= TOPN && nxt < TOPN) { gsel = t; above_s = nxt; }
    __syncthreads();
    int g = gsel;
    unsigned int above = above_s;
    unsigned int fv = g_hist[g * 256 + t];
    __syncthreads();
    s[t] = fv;
    __syncthreads();
    for (int off = 1; off < 256; off <<= 1) {
        unsigned int v = (t + off < 256) ? s[t + off] : 0u;
        __syncthreads();
        s[t] += v;
        __syncthreads();
    }
    unsigned int nxt2 = (t == 255) ? 0u : s[t + 1];
    if (above + s[t] >= TOPN && above + nxt2 < TOPN) {
        g_thresh = (unsigned int)(g * 256 + t);
    }
}

// ---------------- K3: compact candidates ----------------
__global__ void k_compact() {
    int i = blockIdx.x * blockDim.x + threadIdx.x;
    if (i >= NTOT) return;
    unsigned long long key = g_keys[i];
    unsigned int bucket = (unsigned int)(key >> 48);
    if (bucket >= g_thresh) {
        unsigned int pos = atomicAdd(&g_cand_count, 1u);
        if (pos < CAND_MAX) g_cand[pos] = key;
    }
}

// ---------------- K4a: exact rank by counting (keys unique), 2 keys/thread ----
__global__ void k_rank() {
    __shared__ unsigned long long sk[256];
    unsigned int C = g_cand_count;
    if (C > CAND_MAX) C = CAND_MAX;
    int ibase = blockIdx.x * (RB * KPT);
    if (ibase >= (int)C) return;                   // uniform per block
    int i0 = ibase + threadIdx.x;
    int i1 = i0 + RB;
    unsigned long long k0 = (i0 < (int)C) ? g_cand[i0] : 0ull;
    unsigned long long k1 = (i1 < (int)C) ? g_cand[i1] : 0ull;
    int jbeg = blockIdx.y * JCHUNK;
    int jend = jbeg + JCHUNK;
    if (jend > (int)C) jend = (int)C;
    unsigned int c0 = 0, c1 = 0;
    for (int t0 = jbeg; t0 < jend; t0 += 256) {
        int n = jend - t0; if (n > 256) n = 256;
        for (int t = threadIdx.x; t < n; t += RB) sk[t] = g_cand[t0 + t];
        __syncthreads();
#pragma unroll 8
        for (int t = 0; t < n; t++) {
            unsigned long long v = sk[t];
            c0 += (v > k0) ? 1u : 0u;
            c1 += (v > k1) ? 1u : 0u;
        }
        __syncthreads();
    }
    if (i0 < (int)C && c0) atomicAdd(&g_rank[i0], c0);
    if (i1 < (int)C && c1) atomicAdd(&g_rank[i1], c1);
}

// ---------------- K4b: scatter boxes to their rank slot ----------------
__global__ void k_scatter() {
    unsigned int C = g_cand_count;
    if (C > CAND_MAX) C = CAND_MAX;
    int i = blockIdx.x * blockDim.x + threadIdx.x;
    if (i >= (int)C) return;
    unsigned int r = g_rank[i];
    if (r < TOPN) {
        unsigned long long key = g_cand[i];
        unsigned int idx = 0xFFFFFFFFu - (unsigned int)(key & 0xFFFFFFFFull);
        unsigned int a = idx % NA;
        unsigned int k = idx / NA;
        g_top_boxes[r] = g_boxes[a * HW + k];
        g_vld[r] = ((unsigned int)(key >> 32)) > 0x007FFFFFu;
    }
}

// ---------------- K5: fused greedy NMS + collect (single block) ----------------
// All serial-scan control flow is uniform across the block (branch data
// identical per thread), so __syncthreads inside the loop is legal.
__global__ void k_nms(float* __restrict__ out) {
    extern __shared__ char sh[];
    float4* sb = (float4*)sh;                               // [TOPN] boxes
    unsigned long long* remv = (unsigned long long*)(sb + TOPN);  // [NB]
    int tid = threadIdx.x;                                  // 1024 threads

    for (int t = tid; t < TOPN; t += 1024) sb[t] = g_top_boxes[t];
    for (int w = tid; w < NB; w += 1024) {
        unsigned long long m = 0ull;
        for (int bit = 0; bit < 64; bit++) {
            int idx = w * 64 + bit;
            if (idx >= TOPN || !g_vld[idx]) m |= (1ull << bit);
        }
        remv[w] = m;   // invalid/out-of-range start suppressed
    }
    __syncthreads();

    int kept = 0;
    int i = 0;
    while (i < TOPN && kept < POSTN) {
        int w = i >> 6;
        unsigned long long r = remv[w];
        unsigned long long avail = ~r & (~0ull << (i & 63));
        if (avail == 0ull) { i = (w + 1) << 6; continue; }
        int bit = __ffsll((long long)avail) - 1;
        i = (w << 6) + bit;

        float4 bi = sb[i];
        if (tid == 0) {
            float* row = out + kept * 5;
            row[0] = 0.f; row[1] = bi.x; row[2] = bi.y; row[3] = bi.z; row[4] = bi.w;
        }
        kept++;
        if (kept >= POSTN) break;

        float area_i = (bi.z - bi.x) * (bi.w - bi.y);
        for (int j = i + 1 + tid; j < TOPN; j += 1024) {
            float4 bj = sb[j];
            float ix1 = fmaxf(bi.x, bj.x);
            float iy1 = fmaxf(bi.y, bj.y);
            float ix2 = fminf(bi.z, bj.z);
            float iy2 = fminf(bi.w, bj.w);
            float inter = fmaxf(ix2 - ix1, 0.f) * fmaxf(iy2 - iy1, 0.f);
            float area_j = (bj.z - bj.x) * (bj.w - bj.y);
            float denom = fmaxf(area_i + area_j - inter, 1e-9f);
            if (inter > 0.7f * denom)
                atomicOr(&remv[j >> 6], 1ull << (j & 63));
        }
        __syncthreads();
        i++;
    }
}

extern "C" void kernel_launch(void* const* d_in, const int* in_sizes, int n_in,
                              void* d_out, int out_size) {
    const float* scores  = (const float*)d_in[0];
    const float* deltas  = (const float*)d_in[1];
    const float* im_info = (const float*)d_in[2];
    float* out = (float*)d_out;

    void* p;
    cudaGetSymbolAddress(&p, g_hist);
    cudaMemsetAsync(p, 0, 65536 * sizeof(unsigned int));
    cudaGetSymbolAddress(&p, g_cand_count);
    cudaMemsetAsync(p, 0, sizeof(unsigned int));
    cudaGetSymbolAddress(&p, g_rank);
    cudaMemsetAsync(p, 0, CAND_MAX * sizeof(unsigned int));
    cudaMemsetAsync(d_out, 0, POSTN * 5 * sizeof(float));

    k_score_box<<<(NTOT + 255) / 256, 256>>>(scores, deltas, im_info);
    k_thresh<<<1, 256>>>();
    k_compact<<<(NTOT + 255) / 256, 256>>>();

    dim3 gr(CAND_MAX / (RB * KPT), JCHUNKS);
    k_rank<<<gr, RB>>>();
    k_scatter<<<CAND_MAX / 256, 256>>>();

    size_t nsh = (size_t)TOPN * sizeof(float4) + NB * sizeof(unsigned long long);
    cudaFuncSetAttribute(k_nms, cudaFuncAttributeMaxDynamicSharedMemorySize, (int)nsh);
    k_nms<<<1, 1024, nsh>>>(out);
}

// round 4
// speedup vs baseline: 1.9960x; 1.9960x over previous
#include <cuda_runtime.h>
#include <cuda_bf16.h>
#include <cstdint>

#define HF 128
#define WF 192
#define NA 9
#define HW (HF*WF)               // 24576
#define NTOT (HW*NA)             // 221184
#define TOPN 6000
#define POSTN 300
#define NB 94                    // ceil(6000/64)
#define TILE_WORDS (64*NB)       // 6016
#define CAND_MAX 16384
#define CTH 512                  // collect threads

__constant__ float c_anchors[NA][4] = {
    {-84.f,  -40.f,  99.f,  55.f},
    {-176.f, -88.f,  191.f, 103.f},
    {-360.f, -184.f, 375.f, 199.f},
    {-56.f,  -56.f,  71.f,  71.f},
    {-120.f, -120.f, 135.f, 135.f},
    {-248.f, -248.f, 263.f, 263.f},
    {-36.f,  -80.f,  51.f,  95.f},
    {-80.f,  -168.f, 95.f,  183.f},
    {-168.f, -344.f, 183.f, 359.f}
};

__device__ __align__(16) unsigned int g_hist[65536];
__device__ unsigned long long g_keys[NTOT];
__device__ float4 g_boxes[NTOT];          // indexed t = a*HW + k
__device__ unsigned int g_thresh;
__device__ unsigned int g_cand_count;
__device__ __align__(16) unsigned long long g_cand[CAND_MAX];
__device__ float4 g_top_boxes[TOPN];
__device__ unsigned long long g_sup[NB];  // rank-slot invalid bits
__device__ unsigned long long g_mask[6016 * NB];

__device__ __forceinline__ void cp_async8(void* smem_dst, const void* gmem_src) {
    unsigned int d = (unsigned int)__cvta_generic_to_shared(smem_dst);
    asm volatile("cp.async.ca.shared.global [%0], [%1], 8;" :: "r"(d), "l"(gmem_src) : "memory");
}
__device__ __forceinline__ void cp_async_commit() {
    asm volatile("cp.async.commit_group;" ::: "memory");
}
__device__ __forceinline__ void cp_async_wait0() {
    asm volatile("cp.async.wait_group 0;" ::: "memory");
}

// ---------------- K1: decode + keys + histogram (coalesced) ----------------
__global__ void k_score_box(const float* __restrict__ scores,
                            const float* __restrict__ deltas,
                            const float* __restrict__ im_info) {
    int t = blockIdx.x * blockDim.x + threadIdx.x;
    if (t >= NTOT) return;
    int a = t / HW;
    int k = t - a * HW;
    int xs = k >> 7;          // meshgrid 'ij' quirk: shift row k -> (x=k/128, y=k%128)
    int ys = k & 127;
    int i_ref = k * NA + a;   // reference flatten order (tiebreak)

    float sc = scores[(NA + a) * HW + k];
    float dx = deltas[(4*a + 0) * HW + k];
    float dy = deltas[(4*a + 1) * HW + k];
    float dw = deltas[(4*a + 2) * HW + k];
    float dh = deltas[(4*a + 3) * HW + k];

    float sx = 16.f * (float)xs;
    float sy = 16.f * (float)ys;
    float ax1 = c_anchors[a][0] + sx;
    float ay1 = c_anchors[a][1] + sy;
    float ax2 = c_anchors[a][2] + sx;
    float ay2 = c_anchors[a][3] + sy;

    float w = ax2 - ax1 + 1.f;
    float h = ay2 - ay1 + 1.f;
    float cx = ax1 + 0.5f * w;
    float cy = ay1 + 0.5f * h;

    float pcx = dx * w + cx;
    float pcy = dy * h + cy;
    float pw = expf(dw) * w;
    float ph = expf(dh) * h;

    float x1 = pcx - 0.5f * pw;
    float y1 = pcy - 0.5f * ph;
    float x2 = pcx + 0.5f * pw;
    float y2 = pcy + 0.5f * ph;

    float im0 = im_info[0], im1 = im_info[1], im2 = im_info[2];
    x1 = fminf(fmaxf(x1, 0.f), im1 - 1.f);
    x2 = fminf(fmaxf(x2, 0.f), im1 - 1.f);
    y1 = fminf(fmaxf(y1, 0.f), im0 - 1.f);
    y2 = fminf(fmaxf(y2, 0.f), im0 - 1.f);

    float ms = 16.f * im2;
    bool valid = (x2 - x1 + 1.f >= ms) && (y2 - y1 + 1.f >= ms);

    unsigned int srt;
    if (valid) {
        unsigned int b = __float_as_uint(sc);
        srt = (b & 0x80000000u) ? ~b : (b | 0x80000000u);
    } else {
        srt = 0x007FFFFFu;   // flip(-inf)
    }
    unsigned long long key =
        ((unsigned long long)srt << 32) | (0xFFFFFFFFu - (unsigned int)i_ref);
    g_keys[t] = key;
    g_boxes[t] = make_float4(x1, y1, x2, y2);
    atomicAdd(&g_hist[srt >> 16], 1u);
}

// ---------------- K2: find top-6000 threshold bucket ----------------
__global__ void k_thresh() {
    __shared__ unsigned int s[256];
    __shared__ int gsel;
    __shared__ unsigned int above_s;
    int t = threadIdx.x;
    unsigned int sum = 0;
    const uint4* h4 = (const uint4*)g_hist;
#pragma unroll 8
    for (int b = 0; b < 64; b++) {
        uint4 v = h4[t * 64 + b];
        sum += v.x + v.y + v.z + v.w;
    }
    s[t] = sum;
    __syncthreads();
    for (int off = 1; off < 256; off <<= 1) {
        unsigned int v = (t + off < 256) ? s[t + off] : 0u;
        __syncthreads();
        s[t] += v;
        __syncthreads();
    }
    unsigned int nxt = (t == 255) ? 0u : s[t + 1];
    if (s[t] >= TOPN && nxt < TOPN) { gsel = t; above_s = nxt; }
    __syncthreads();
    int g = gsel;
    unsigned int above = above_s;
    unsigned int fv = g_hist[g * 256 + t];
    __syncthreads();
    s[t] = fv;
    __syncthreads();
    for (int off = 1; off < 256; off <<= 1) {
        unsigned int v = (t + off < 256) ? s[t + off] : 0u;
        __syncthreads();
        s[t] += v;
        __syncthreads();
    }
    unsigned int nxt2 = (t == 255) ? 0u : s[t + 1];
    if (above + s[t] >= TOPN && above + nxt2 < TOPN) {
        g_thresh = (unsigned int)(g * 256 + t);
    }
}

// ---------------- K3: compact candidates ----------------
__global__ void k_compact() {
    int i = blockIdx.x * blockDim.x + threadIdx.x;
    if (i >= NTOT) return;
    unsigned long long key = g_keys[i];
    unsigned int bucket = (unsigned int)(key >> 48);
    if (bucket >= g_thresh) {
        unsigned int pos = atomicAdd(&g_cand_count, 1u);
        if (pos < CAND_MAX) g_cand[pos] = key;
    }
}

// ---------------- K4: fused exact rank (count) + scatter ----------------
__global__ void k_ranksc() {
    __shared__ __align__(16) unsigned long long sk[512];
    unsigned int C = g_cand_count;
    if (C > CAND_MAX) C = CAND_MAX;
    if (blockIdx.x * 256 >= (int)C) return;       // uniform per block
    int i = blockIdx.x * 256 + threadIdx.x;
    unsigned long long mykey = (i < (int)C) ? g_cand[i] : 0ull;
    unsigned int cnt = 0;
    for (int t0 = 0; t0 < (int)C; t0 += 512) {
        int n = (int)C - t0; if (n > 512) n = 512;
        for (int t = threadIdx.x; t < n; t += 256) sk[t] = g_cand[t0 + t];
        if ((n & 1) && threadIdx.x == 0) sk[n] = 0ull;  // pad for vector loop
        __syncthreads();
        int nv = (n + 1) >> 1;
        const ulonglong2* sk2 = (const ulonglong2*)sk;
#pragma unroll 4
        for (int t = 0; t < nv; t++) {
            ulonglong2 v = sk2[t];
            cnt += (v.x > mykey) ? 1u : 0u;
            cnt += (v.y > mykey) ? 1u : 0u;
        }
        __syncthreads();
    }
    if (i < (int)C && cnt < TOPN) {
        unsigned int idx = 0xFFFFFFFFu - (unsigned int)(mykey & 0xFFFFFFFFull);
        unsigned int a = idx % NA;
        unsigned int k = idx / NA;
        g_top_boxes[cnt] = g_boxes[a * HW + k];
        bool valid = ((unsigned int)(mykey >> 32)) > 0x007FFFFFu;
        if (!valid) atomicOr(&g_sup[cnt >> 6], 1ull << (cnt & 63));
    }
}

// ---------------- K5: NMS suppression bitmask (upper triangle only) ----------------
__global__ void k_mask() {
    int bi = blockIdx.y, bj = blockIdx.x;
    if (bj < bi) return;
    int t = threadIdx.x;
    int i = bi * 64 + t;
    __shared__ float4 bb[64];
    __shared__ float ar[64];
    int jg0 = bj * 64 + t;
    if (jg0 < TOPN) {
        float4 b = g_top_boxes[jg0];
        bb[t] = b;
        ar[t] = (b.z - b.x) * (b.w - b.y);
    } else {
        bb[t] = make_float4(0.f, 0.f, 0.f, 0.f);
        ar[t] = 0.f;
    }
    __syncthreads();
    if (i >= TOPN) return;
    float4 bi_box = g_top_boxes[i];
    float area_i = (bi_box.z - bi_box.x) * (bi_box.w - bi_box.y);
    unsigned long long m = 0ull;
#pragma unroll 4
    for (int jj = 0; jj < 64; jj++) {
        int jg = bj * 64 + jj;
        float4 bj_box = bb[jj];
        float ix1 = fmaxf(bi_box.x, bj_box.x);
        float iy1 = fmaxf(bi_box.y, bj_box.y);
        float ix2 = fminf(bi_box.z, bj_box.z);
        float iy2 = fminf(bi_box.w, bj_box.w);
        float inter = fmaxf(ix2 - ix1, 0.f) * fmaxf(iy2 - iy1, 0.f);
        float denom = fmaxf(area_i + ar[jj] - inter, 1e-9f);
        float iou = inter / denom;
        if (iou > 0.7f && jg > i && jg < TOPN) m |= (1ull << jj);
    }
    g_mask[(size_t)i * NB + bj] = m;
}

// ---------------- K6: greedy collect, deferred-OR, cp.async double buffer ----
// Control flow uniform across block (branch data identical per thread).
__global__ void __launch_bounds__(CTH) k_collect(float* __restrict__ out) {
    __shared__ unsigned long long remv[NB];
    __shared__ int klist[POSTN];
    extern __shared__ unsigned long long tiles[];  // 2 * TILE_WORDS
    int tid = threadIdx.x;

    for (int t = tid; t < NB; t += CTH) {
        unsigned long long m = g_sup[t];
        if (t == NB - 1) m |= 0xFFFF000000000000ull;   // bits 48..63 (>= 6000)
        remv[t] = m;
    }

    // prefetch tile 0
    {
        int wcnt = NB;
        for (int t = tid; t < 64 * wcnt; t += CTH) {
            int r = t / wcnt, w = t - r * wcnt;
            cp_async8(&tiles[t], &g_mask[(size_t)r * NB + w]);
        }
        cp_async_commit();
    }
    cp_async_wait0();
    __syncthreads();

    int kept = 0;
    for (int ib = 0; ib < NB; ib++) {
        unsigned long long* tile = tiles + (size_t)(ib & 1) * TILE_WORDS;
        // issue prefetch of next tile into the other buffer
        if (ib + 1 < NB) {
            int nb2 = ib + 1;
            int wcnt2 = NB - nb2;
            int rows2 = TOPN - nb2 * 64; if (rows2 > 64) rows2 = 64;
            unsigned long long* dst = tiles + (size_t)(nb2 & 1) * TILE_WORDS;
            for (int t = tid; t < rows2 * wcnt2; t += CTH) {
                int r = t / wcnt2, w = t - r * wcnt2;
                cp_async8(&dst[t], &g_mask[(size_t)(nb2 * 64 + r) * NB + nb2 + w]);
            }
        }
        cp_async_commit();

        int wcnt = NB - ib;
        unsigned long long rcur = remv[ib];
        unsigned long long acc = 0ull;
        int w = tid;                       // this thread owns word ib+w (w<wcnt)
        while (true) {
            unsigned long long avail = ~rcur;
            if (avail == 0ull) break;
            int bit = __ffsll((long long)avail) - 1;
            if (tid == 0) klist[kept] = ib * 64 + bit;
            kept++;
            rcur |= tile[bit * wcnt] | (1ull << bit);      // self word + mark done
            if (w > 0 && w < wcnt) acc |= tile[bit * wcnt + w];
            if (kept >= POSTN) break;
        }
        if (w > 0 && w < wcnt) remv[ib + w] |= acc;
        if (kept >= POSTN) break;
        cp_async_wait0();
        __syncthreads();
    }

    cp_async_wait0();
    __syncthreads();
    if (tid < kept) {
        int idx = klist[tid];
        float4 b = g_top_boxes[idx];
        float* row = out + tid * 5;
        row[0] = 0.f; row[1] = b.x; row[2] = b.y; row[3] = b.z; row[4] = b.w;
    }
}

extern "C" void kernel_launch(void* const* d_in, const int* in_sizes, int n_in,
                              void* d_out, int out_size) {
    const float* scores  = (const float*)d_in[0];
    const float* deltas  = (const float*)d_in[1];
    const float* im_info = (const float*)d_in[2];
    float* out = (float*)d_out;

    void* p;
    cudaGetSymbolAddress(&p, g_hist);
    cudaMemsetAsync(p, 0, 65536 * sizeof(unsigned int));
    cudaGetSymbolAddress(&p, g_cand_count);
    cudaMemsetAsync(p, 0, sizeof(unsigned int));
    cudaGetSymbolAddress(&p, g_sup);
    cudaMemsetAsync(p, 0, NB * sizeof(unsigned long long));
    cudaMemsetAsync(d_out, 0, POSTN * 5 * sizeof(float));

    k_score_box<<<(NTOT + 255) / 256, 256>>>(scores, deltas, im_info);
    k_thresh<<<1, 256>>>();
    k_compact<<<(NTOT + 255) / 256, 256>>>();
    k_ranksc<<<CAND_MAX / 256, 256>>>();

    dim3 gm(NB, NB);
    k_mask<<<gm, 64>>>();

    size_t csh = (size_t)2 * TILE_WORDS * sizeof(unsigned long long);
    cudaFuncSetAttribute(k_collect, cudaFuncAttributeMaxDynamicSharedMemorySize, (int)csh);
    k_collect<<<1, CTH, csh>>>(out);
}

// round 5
// speedup vs baseline: 2.4764x; 1.2407x over previous
#include <cuda_runtime.h>
#include <cuda_bf16.h>
#include <cstdint>

#define HF 128
#define WF 192
#define NA 9
#define HW (HF*WF)               // 24576
#define NTOT (HW*NA)             // 221184
#define TOPN 6000
#define POSTN 300
#define NB 94                    // ceil(6000/64)
#define TILE_WORDS (64*NB)       // 6016
#define CAND_MAX 16384
#define CTH 512                  // collect threads
#define JCHUNKS 32
#define JCHUNK (CAND_MAX/JCHUNKS) // 512

__constant__ float c_anchors[NA][4] = {
    {-84.f,  -40.f,  99.f,  55.f},
    {-176.f, -88.f,  191.f, 103.f},
    {-360.f, -184.f, 375.f, 199.f},
    {-56.f,  -56.f,  71.f,  71.f},
    {-120.f, -120.f, 135.f, 135.f},
    {-248.f, -248.f, 263.f, 263.f},
    {-36.f,  -80.f,  51.f,  95.f},
    {-80.f,  -168.f, 95.f,  183.f},
    {-168.f, -344.f, 183.f, 359.f}
};

__device__ __align__(16) unsigned int g_hist[65536];
__device__ unsigned long long g_keys[NTOT];
__device__ float4 g_boxes[NTOT];          // indexed t = a*HW + k
__device__ unsigned int g_thresh;
__device__ unsigned int g_cand_count;
__device__ __align__(16) unsigned long long g_cand[CAND_MAX];
__device__ unsigned int g_rank[CAND_MAX];
__device__ float4 g_top_boxes[TOPN];
__device__ unsigned long long g_sup[NB];  // rank-slot invalid bits
__device__ unsigned long long g_mask[6016 * NB];

__device__ __forceinline__ void cp_async8(void* smem_dst, const void* gmem_src) {
    unsigned int d = (unsigned int)__cvta_generic_to_shared(smem_dst);
    asm volatile("cp.async.ca.shared.global [%0], [%1], 8;" :: "r"(d), "l"(gmem_src) : "memory");
}
__device__ __forceinline__ void cp_async_commit() {
    asm volatile("cp.async.commit_group;" ::: "memory");
}
__device__ __forceinline__ void cp_async_wait0() {
    asm volatile("cp.async.wait_group 0;" ::: "memory");
}

// ---------------- K1: decode + keys + histogram (coalesced) ----------------
__global__ void k_score_box(const float* __restrict__ scores,
                            const float* __restrict__ deltas,
                            const float* __restrict__ im_info) {
    int t = blockIdx.x * blockDim.x + threadIdx.x;
    if (t >= NTOT) return;
    int a = t / HW;
    int k = t - a * HW;
    int xs = k >> 7;          // meshgrid 'ij' quirk: shift row k -> (x=k/128, y=k%128)
    int ys = k & 127;
    int i_ref = k * NA + a;   // reference flatten order (tiebreak)

    float sc = scores[(NA + a) * HW + k];
    float dx = deltas[(4*a + 0) * HW + k];
    float dy = deltas[(4*a + 1) * HW + k];
    float dw = deltas[(4*a + 2) * HW + k];
    float dh = deltas[(4*a + 3) * HW + k];

    float sx = 16.f * (float)xs;
    float sy = 16.f * (float)ys;
    float ax1 = c_anchors[a][0] + sx;
    float ay1 = c_anchors[a][1] + sy;
    float ax2 = c_anchors[a][2] + sx;
    float ay2 = c_anchors[a][3] + sy;

    float w = ax2 - ax1 + 1.f;
    float h = ay2 - ay1 + 1.f;
    float cx = ax1 + 0.5f * w;
    float cy = ay1 + 0.5f * h;

    float pcx = dx * w + cx;
    float pcy = dy * h + cy;
    float pw = expf(dw) * w;
    float ph = expf(dh) * h;

    float x1 = pcx - 0.5f * pw;
    float y1 = pcy - 0.5f * ph;
    float x2 = pcx + 0.5f * pw;
    float y2 = pcy + 0.5f * ph;

    float im0 = im_info[0], im1 = im_info[1], im2 = im_info[2];
    x1 = fminf(fmaxf(x1, 0.f), im1 - 1.f);
    x2 = fminf(fmaxf(x2, 0.f), im1 - 1.f);
    y1 = fminf(fmaxf(y1, 0.f), im0 - 1.f);
    y2 = fminf(fmaxf(y2, 0.f), im0 - 1.f);

    float ms = 16.f * im2;
    bool valid = (x2 - x1 + 1.f >= ms) && (y2 - y1 + 1.f >= ms);

    unsigned int srt;
    if (valid) {
        unsigned int b = __float_as_uint(sc);
        srt = (b & 0x80000000u) ? ~b : (b | 0x80000000u);
    } else {
        srt = 0x007FFFFFu;   // flip(-inf)
    }
    unsigned long long key =
        ((unsigned long long)srt << 32) | (0xFFFFFFFFu - (unsigned int)i_ref);
    g_keys[t] = key;
    g_boxes[t] = make_float4(x1, y1, x2, y2);
    atomicAdd(&g_hist[srt >> 16], 1u);
}

// ---------------- K2: find top-6000 threshold bucket ----------------
__global__ void k_thresh() {
    __shared__ unsigned int s[256];
    __shared__ int gsel;
    __shared__ unsigned int above_s;
    int t = threadIdx.x;
    unsigned int sum = 0;
    const uint4* h4 = (const uint4*)g_hist;
#pragma unroll 8
    for (int b = 0; b < 64; b++) {
        uint4 v = h4[t * 64 + b];
        sum += v.x + v.y + v.z + v.w;
    }
    s[t] = sum;
    __syncthreads();
    for (int off = 1; off < 256; off <<= 1) {
        unsigned int v = (t + off < 256) ? s[t + off] : 0u;
        __syncthreads();
        s[t] += v;
        __syncthreads();
    }
    unsigned int nxt = (t == 255) ? 0u : s[t + 1];
    if (s[t] >= TOPN && nxt < TOPN) { gsel = t; above_s = nxt; }
    __syncthreads();
    int g = gsel;
    unsigned int above = above_s;
    unsigned int fv = g_hist[g * 256 + t];
    __syncthreads();
    s[t] = fv;
    __syncthreads();
    for (int off = 1; off < 256; off <<= 1) {
        unsigned int v = (t + off < 256) ? s[t + off] : 0u;
        __syncthreads();
        s[t] += v;
        __syncthreads();
    }
    unsigned int nxt2 = (t == 255) ? 0u : s[t + 1];
    if (above + s[t] >= TOPN && above + nxt2 < TOPN) {
        g_thresh = (unsigned int)(g * 256 + t);
    }
}

// ---------------- K3: compact candidates ----------------
__global__ void k_compact() {
    int i = blockIdx.x * blockDim.x + threadIdx.x;
    if (i >= NTOT) return;
    unsigned long long key = g_keys[i];
    unsigned int bucket = (unsigned int)(key >> 48);
    if (bucket >= g_thresh) {
        unsigned int pos = atomicAdd(&g_cand_count, 1u);
        if (pos < CAND_MAX) g_cand[pos] = key;
    }
}

// ---------------- K4a: exact rank by counting, fine j-chunks ----------------
__global__ void k_rank() {
    __shared__ __align__(16) unsigned long long sk[JCHUNK + 1];
    unsigned int C = g_cand_count;
    if (C > CAND_MAX) C = CAND_MAX;
    if (blockIdx.x * 256 >= (int)C) return;        // uniform per block
    int jbeg = blockIdx.y * JCHUNK;
    if (jbeg >= (int)C) return;                    // uniform per block
    int i = blockIdx.x * 256 + threadIdx.x;
    unsigned long long mykey = (i < (int)C) ? g_cand[i] : 0ull;
    int n = (int)C - jbeg; if (n > JCHUNK) n = JCHUNK;
    for (int t = threadIdx.x; t < n; t += 256) sk[t] = g_cand[jbeg + t];
    if (threadIdx.x == 0 && (n & 1)) sk[n] = 0ull;
    __syncthreads();
    unsigned int cnt = 0;
    int nv = (n + 1) >> 1;
    const ulonglong2* sk2 = (const ulonglong2*)sk;
#pragma unroll 8
    for (int t = 0; t < nv; t++) {
        ulonglong2 v = sk2[t];
        cnt += (v.x > mykey) ? 1u : 0u;
        cnt += (v.y > mykey) ? 1u : 0u;
    }
    if (i < (int)C && cnt) atomicAdd(&g_rank[i], cnt);
}

// ---------------- K4b: scatter boxes to their rank slot ----------------
__global__ void k_scatter() {
    unsigned int C = g_cand_count;
    if (C > CAND_MAX) C = CAND_MAX;
    int i = blockIdx.x * blockDim.x + threadIdx.x;
    if (i >= (int)C) return;
    unsigned int r = g_rank[i];
    if (r < TOPN) {
        unsigned long long key = g_cand[i];
        unsigned int idx = 0xFFFFFFFFu - (unsigned int)(key & 0xFFFFFFFFull);
        unsigned int a = idx % NA;
        unsigned int k = idx / NA;
        g_top_boxes[r] = g_boxes[a * HW + k];
        bool valid = ((unsigned int)(key >> 32)) > 0x007FFFFFu;
        if (!valid) atomicOr(&g_sup[r >> 6], 1ull << (r & 63));
    }
}

// ---------------- K5: NMS suppression bitmask (upper triangle only) ----------------
__global__ void k_mask() {
    int bi = blockIdx.y, bj = blockIdx.x;
    if (bj < bi) return;
    int t = threadIdx.x;
    int i = bi * 64 + t;
    __shared__ float4 bb[64];
    __shared__ float ar[64];
    int jg0 = bj * 64 + t;
    if (jg0 < TOPN) {
        float4 b = g_top_boxes[jg0];
        bb[t] = b;
        ar[t] = (b.z - b.x) * (b.w - b.y);
    } else {
        bb[t] = make_float4(0.f, 0.f, 0.f, 0.f);
        ar[t] = 0.f;
    }
    __syncthreads();
    if (i >= TOPN) return;
    float4 bi_box = g_top_boxes[i];
    float area_i = (bi_box.z - bi_box.x) * (bi_box.w - bi_box.y);
    unsigned long long m = 0ull;
#pragma unroll 4
    for (int jj = 0; jj < 64; jj++) {
        int jg = bj * 64 + jj;
        float4 bj_box = bb[jj];
        float ix1 = fmaxf(bi_box.x, bj_box.x);
        float iy1 = fmaxf(bi_box.y, bj_box.y);
        float ix2 = fminf(bi_box.z, bj_box.z);
        float iy2 = fminf(bi_box.w, bj_box.w);
        float inter = fmaxf(ix2 - ix1, 0.f) * fmaxf(iy2 - iy1, 0.f);
        float denom = fmaxf(area_i + ar[jj] - inter, 1e-9f);
        float iou = inter / denom;
        if (iou > 0.7f && jg > i && jg < TOPN) m |= (1ull << jj);
    }
    g_mask[(size_t)i * NB + bj] = m;
}

// ---------------- K6: greedy collect, deferred-OR, cp.async double buffer ----
// Control flow uniform across block (branch data identical per thread).
__global__ void __launch_bounds__(CTH) k_collect(float* __restrict__ out) {
    __shared__ unsigned long long remv[NB];
    __shared__ int klist[POSTN];
    extern __shared__ unsigned long long tiles[];  // 2 * TILE_WORDS
    int tid = threadIdx.x;

    for (int t = tid; t < NB; t += CTH) {
        unsigned long long m = g_sup[t];
        if (t == NB - 1) m |= 0xFFFF000000000000ull;   // bits 48..63 (>= 6000)
        remv[t] = m;
    }

    // prefetch tile 0
    {
        int wcnt = NB;
        for (int t = tid; t < 64 * wcnt; t += CTH) {
            int r = t / wcnt, w = t - r * wcnt;
            cp_async8(&tiles[t], &g_mask[(size_t)r * NB + w]);
        }
        cp_async_commit();
    }
    cp_async_wait0();
    __syncthreads();

    int kept = 0;
    for (int ib = 0; ib < NB; ib++) {
        unsigned long long* tile = tiles + (size_t)(ib & 1) * TILE_WORDS;
        // issue prefetch of next tile into the other buffer
        if (ib + 1 < NB) {
            int nb2 = ib + 1;
            int wcnt2 = NB - nb2;
            int rows2 = TOPN - nb2 * 64; if (rows2 > 64) rows2 = 64;
            unsigned long long* dst = tiles + (size_t)(nb2 & 1) * TILE_WORDS;
            for (int t = tid; t < rows2 * wcnt2; t += CTH) {
                int r = t / wcnt2, w = t - r * wcnt2;
                cp_async8(&dst[t], &g_mask[(size_t)(nb2 * 64 + r) * NB + nb2 + w]);
            }
        }
        cp_async_commit();

        int wcnt = NB - ib;
        unsigned long long rcur = remv[ib];
        unsigned long long acc = 0ull;
        int w = tid;                       // this thread owns word ib+w (w<wcnt)
        while (true) {
            unsigned long long avail = ~rcur;
            if (avail == 0ull) break;
            int bit = __ffsll((long long)avail) - 1;
            if (tid == 0) klist[kept] = ib * 64 + bit;
            kept++;
            rcur |= tile[bit * wcnt] | (1ull << bit);      // self word + mark done
            if (w > 0 && w < wcnt) acc |= tile[bit * wcnt + w];
            if (kept >= POSTN) break;
        }
        if (w > 0 && w < wcnt) remv[ib + w] |= acc;
        if (kept >= POSTN) break;
        cp_async_wait0();
        __syncthreads();
    }

    cp_async_wait0();
    __syncthreads();
    if (tid < kept) {
        int idx = klist[tid];
        float4 b = g_top_boxes[idx];
        float* row = out + tid * 5;
        row[0] = 0.f; row[1] = b.x; row[2] = b.y; row[3] = b.z; row[4] = b.w;
    }
}

extern "C" void kernel_launch(void* const* d_in, const int* in_sizes, int n_in,
                              void* d_out, int out_size) {
    const float* scores  = (const float*)d_in[0];
    const float* deltas  = (const float*)d_in[1];
    const float* im_info = (const float*)d_in[2];
    float* out = (float*)d_out;

    void* p;
    cudaGetSymbolAddress(&p, g_hist);
    cudaMemsetAsync(p, 0, 65536 * sizeof(unsigned int));
    cudaGetSymbolAddress(&p, g_cand_count);
    cudaMemsetAsync(p, 0, sizeof(unsigned int));
    cudaGetSymbolAddress(&p, g_rank);
    cudaMemsetAsync(p, 0, CAND_MAX * sizeof(unsigned int));
    cudaGetSymbolAddress(&p, g_sup);
    cudaMemsetAsync(p, 0, NB * sizeof(unsigned long long));
    cudaMemsetAsync(d_out, 0, POSTN * 5 * sizeof(float));

    k_score_box<<<(NTOT + 255) / 256, 256>>>(scores, deltas, im_info);
    k_thresh<<<1, 256>>>();
    k_compact<<<(NTOT + 255) / 256, 256>>>();

    dim3 gr(CAND_MAX / 256, JCHUNKS);
    k_rank<<<gr, 256>>>();
    k_scatter<<<CAND_MAX / 256, 256>>>();

    dim3 gm(NB, NB);
    k_mask<<<gm, 64>>>();

    size_t csh = (size_t)2 * TILE_WORDS * sizeof(unsigned long long);
    cudaFuncSetAttribute(k_collect, cudaFuncAttributeMaxDynamicSharedMemorySize, (int)csh);
    k_collect<<<1, CTH, csh>>>(out);
}